// round 6
// baseline (speedup 1.0000x reference)
#include <cuda_runtime.h>
#include <cuda_bf16.h>
#include <cstdint>

#define NVERT    16384
#define BLOCK    1024
#define GRID     148
#define NWARPS   (GRID * (BLOCK / 32))
#define SMEM_BYTES (3 * NVERT * sizeof(float))   // 196608 B

// Tier A: row-pairs 0..7807, units = pair x 4 quarters of 4096 cols (32 KB)
#define A_PAIRS   7808
#define A_UNITS   (A_PAIRS * 4)          // 31232
#define A_COLS    4096
// Tier B (drain tail): row-pairs 7808..8191, units = pair x 32 slices of 512 cols (4 KB)
#define B_PAIRS   384
#define B_ROW0    (2 * A_PAIRS)          // 15616
#define B_SLICES  32
#define B_COLS    512
#define B_UNITS   (B_PAIRS * B_SLICES)   // 12288
#define NUNITS    (A_UNITS + B_UNITS)    // 43520

// Deterministic partials.
// Tier A rows: y4[q][row][comp], rows 0..15615 used.
__device__ float g_y4[4 * NVERT * 3];
// Tier B rows: yB[s][lrow][comp], lrow = row - 15616 (0..767).
__device__ float g_yB[B_SLICES * (2 * B_PAIRS) * 3];
// Work-stealing state (self-resetting for graph replays)
__device__ unsigned int g_ticket = 0;
__device__ unsigned int g_done   = 0;

__global__ void __launch_bounds__(BLOCK, 1)
lap_main_kernel(const float* __restrict__ L, const float* __restrict__ x,
                float* __restrict__ out) {
    extern __shared__ float sx[];   // SoA: [3][NVERT]

    if (blockIdx.x == 0 && threadIdx.x == 0) out[0] = 0.0f;

    // Stage x into shared memory: SoA, per-vertex
    for (int vert = threadIdx.x; vert < NVERT; vert += BLOCK) {
        float a = x[3 * vert + 0];
        float b = x[3 * vert + 1];
        float c = x[3 * vert + 2];
        sx[0 * NVERT + vert] = a;
        sx[1 * NVERT + vert] = b;
        sx[2 * NVERT + vert] = c;
    }
    __syncthreads();

    const int lane = threadIdx.x & 31;

    for (;;) {
        unsigned int u;
        if (lane == 0) u = atomicAdd(&g_ticket, 1u);
        u = __shfl_sync(0xFFFFFFFFu, u, 0);
        if (u >= NUNITS) break;

        int row0, colbase, niter;   // unit geometry
        if (u < A_UNITS) {
            const int p = (int)(u >> 2);
            const int q = (int)(u & 3);
            row0 = 2 * p;
            colbase = q * A_COLS;
            niter = A_COLS / 4;
        } else {
            const unsigned int t = u - A_UNITS;
            const int p = (int)(t >> 5);
            const int s = (int)(t & (B_SLICES - 1));
            row0 = B_ROW0 + 2 * p;
            colbase = s * B_COLS;
            niter = B_COLS / 4;
        }

        const float4* __restrict__ r0 =
            (const float4*)(L + (size_t)row0 * NVERT + colbase);
        const float4* __restrict__ r1 = r0 + (NVERT / 4);

        const float4* __restrict__ xs0 = (const float4*)(sx + 0 * NVERT + colbase);
        const float4* __restrict__ xs1 = (const float4*)(sx + 1 * NVERT + colbase);
        const float4* __restrict__ xs2 = (const float4*)(sx + 2 * NVERT + colbase);

        float a00 = 0.f, a01 = 0.f, a02 = 0.f;
        float a10 = 0.f, a11 = 0.f, a12 = 0.f;

        #pragma unroll 4
        for (int i = lane; i < niter; i += 32) {
            float4 l0 = __ldcs(r0 + i);   // streaming: L has zero reuse
            float4 l1 = __ldcs(r1 + i);
            float4 v0 = xs0[i];
            float4 v1 = xs1[i];
            float4 v2 = xs2[i];

            a00 += l0.x * v0.x + l0.y * v0.y + l0.z * v0.z + l0.w * v0.w;
            a01 += l0.x * v1.x + l0.y * v1.y + l0.z * v1.z + l0.w * v1.w;
            a02 += l0.x * v2.x + l0.y * v2.y + l0.z * v2.z + l0.w * v2.w;
            a10 += l1.x * v0.x + l1.y * v0.y + l1.z * v0.z + l1.w * v0.w;
            a11 += l1.x * v1.x + l1.y * v1.y + l1.z * v1.z + l1.w * v1.w;
            a12 += l1.x * v2.x + l1.y * v2.y + l1.z * v2.z + l1.w * v2.w;
        }

        #pragma unroll
        for (int off = 16; off > 0; off >>= 1) {
            a00 += __shfl_xor_sync(0xFFFFFFFFu, a00, off);
            a01 += __shfl_xor_sync(0xFFFFFFFFu, a01, off);
            a02 += __shfl_xor_sync(0xFFFFFFFFu, a02, off);
            a10 += __shfl_xor_sync(0xFFFFFFFFu, a10, off);
            a11 += __shfl_xor_sync(0xFFFFFFFFu, a11, off);
            a12 += __shfl_xor_sync(0xFFFFFFFFu, a12, off);
        }

        if (lane < 6) {
            float v;
            switch (lane) {
                case 0: v = a00; break;
                case 1: v = a01; break;
                case 2: v = a02; break;
                case 3: v = a10; break;
                case 4: v = a11; break;
                default: v = a12; break;
            }
            const int row = row0 + (lane >= 3 ? 1 : 0);
            const int c   = (lane >= 3) ? (lane - 3) : lane;
            if (u < A_UNITS) {
                const int q = (int)(u & 3);
                g_y4[(q * NVERT + row) * 3 + c] = v;
            } else {
                const int s = (int)((u - A_UNITS) & (B_SLICES - 1));
                g_yB[(s * (2 * B_PAIRS) + (row - B_ROW0)) * 3 + c] = v;
            }
        }
    }

    // Self-reset: last warp restores counters for the next graph replay.
    if (lane == 0) {
        __threadfence();
        unsigned int d = atomicAdd(&g_done, 1u);
        if (d == NWARPS - 1) {
            g_ticket = 0;
            g_done   = 0;
            __threadfence();
        }
    }
}

__global__ void __launch_bounds__(512)
pass2_kernel(float* __restrict__ out) {
    __shared__ float red[16];
    float s = 0.f;
    const int stride = gridDim.x * blockDim.x;
    const int tid = blockIdx.x * blockDim.x + threadIdx.x;

    // Tier A region: rows 0..15615 -> 15616*3/4 = 11712 float4 per slice.
    {
        const float4* __restrict__ yv = (const float4*)g_y4;
        const int totalA = (B_ROW0 * 3) / 4;             // 11712
        const int sliceStride = (NVERT * 3) / 4;         // 12288 (q-slice stride)
        for (int i = tid; i < totalA; i += stride) {
            float4 a = yv[i];
            float4 b = yv[i + sliceStride];
            float4 c = yv[i + 2 * sliceStride];
            float4 d = yv[i + 3 * sliceStride];
            float vx = a.x + b.x + c.x + d.x;
            float vy = a.y + b.y + c.y + d.y;
            float vz = a.z + b.z + c.z + d.z;
            float vw = a.w + b.w + c.w + d.w;
            s += vx * vx + vy * vy + vz * vz + vw * vw;
        }
    }
    // Tier B region: 768 rows -> 768*3/4 = 576 float4 per slice, 32 slices.
    {
        const float4* __restrict__ yv = (const float4*)g_yB;
        const int totalB = (2 * B_PAIRS * 3) / 4;        // 576
        for (int i = tid; i < totalB; i += stride) {
            float4 a = yv[i];
            #pragma unroll
            for (int j = 1; j < B_SLICES; j++) {
                float4 b = yv[i + j * totalB];
                a.x += b.x; a.y += b.y; a.z += b.z; a.w += b.w;
            }
            s += a.x * a.x + a.y * a.y + a.z * a.z + a.w * a.w;
        }
    }

    #pragma unroll
    for (int off = 16; off > 0; off >>= 1)
        s += __shfl_xor_sync(0xFFFFFFFFu, s, off);
    const int lane = threadIdx.x & 31;
    const int wid  = threadIdx.x >> 5;
    if (lane == 0) red[wid] = s;
    __syncthreads();
    if (wid == 0) {
        int nwarps = blockDim.x >> 5;
        float t = (lane < nwarps) ? red[lane] : 0.f;
        #pragma unroll
        for (int off = 16; off > 0; off >>= 1)
            t += __shfl_xor_sync(0xFFFFFFFFu, t, off);
        if (lane == 0) atomicAdd(out, t);
    }
}

extern "C" void kernel_launch(void* const* d_in, const int* in_sizes, int n_in,
                              void* d_out, int out_size) {
    // Identify inputs by element count: x has NVERT*3, L has NVERT*NVERT.
    const float* x = (const float*)d_in[0];
    const float* L = (const float*)d_in[1];
    if (in_sizes[0] != NVERT * 3) {
        x = (const float*)d_in[1];
        L = (const float*)d_in[0];
    }
    float* out = (float*)d_out;

    cudaFuncSetAttribute(lap_main_kernel,
                         cudaFuncAttributeMaxDynamicSharedMemorySize,
                         (int)SMEM_BYTES);

    lap_main_kernel<<<GRID, BLOCK, SMEM_BYTES>>>(L, x, out);
    pass2_kernel<<<64, 512>>>(out);
}

// round 7
// speedup vs baseline: 1.0238x; 1.0238x over previous
#include <cuda_runtime.h>
#include <cuda_bf16.h>
#include <cstdint>

#define NVERT    16384
#define BLOCK    1024
#define GRID     148
#define NWARPS   (GRID * (BLOCK / 32))
#define SMEM_BYTES (3 * NVERT * sizeof(float))   // 196608 B

// Tier A: row-pairs 0..7679, units = pair x 4 quarters of 4096 cols (32 KB)
#define A_PAIRS   7680
#define A_UNITS   (A_PAIRS * 4)          // 30720
#define A_COLS    4096
// Tier B (drain tail): row-pairs 7680..8191, units = pair x 16 slices of 1024 cols (8 KB)
#define B_PAIRS   512
#define B_ROW0    (2 * A_PAIRS)          // 15360
#define B_SLICES  16
#define B_COLS    1024
#define B_UNITS   (B_PAIRS * B_SLICES)   // 8192
#define NUNITS    (A_UNITS + B_UNITS)    // 38912

// Deterministic partials.
// Tier A rows: y4[q][row][comp], rows 0..15359 used.
__device__ float g_y4[4 * NVERT * 3];
// Tier B rows: yB[s][lrow][comp], lrow = row - 15360 (0..1023).
__device__ float g_yB[B_SLICES * (2 * B_PAIRS) * 3];
// Work-stealing state (reset by finisher block each run)
__device__ unsigned int g_ticket = 0;
__device__ unsigned int g_done   = 0;

__global__ void __launch_bounds__(BLOCK, 1)
lap_fused_kernel(const float* __restrict__ L, const float* __restrict__ x,
                 float* __restrict__ out) {
    extern __shared__ float sx[];   // SoA: [3][NVERT]
    __shared__ float red[32];
    __shared__ int   s_fin;

    if (threadIdx.x == 0) s_fin = 0;

    // Stage x into shared memory: SoA, per-vertex
    for (int vert = threadIdx.x; vert < NVERT; vert += BLOCK) {
        float a = x[3 * vert + 0];
        float b = x[3 * vert + 1];
        float c = x[3 * vert + 2];
        sx[0 * NVERT + vert] = a;
        sx[1 * NVERT + vert] = b;
        sx[2 * NVERT + vert] = c;
    }
    __syncthreads();   // also publishes s_fin = 0

    const int lane = threadIdx.x & 31;

    // ---------------- Phase 1: stream L with work stealing ----------------
    for (;;) {
        unsigned int u;
        if (lane == 0) u = atomicAdd(&g_ticket, 1u);
        u = __shfl_sync(0xFFFFFFFFu, u, 0);
        if (u >= NUNITS) break;

        int row0, colbase, niter;   // unit geometry
        if (u < A_UNITS) {
            const int p = (int)(u >> 2);
            const int q = (int)(u & 3);
            row0 = 2 * p;
            colbase = q * A_COLS;
            niter = A_COLS / 4;
        } else {
            const unsigned int t = u - A_UNITS;
            const int p = (int)(t >> 4);
            const int s = (int)(t & (B_SLICES - 1));
            row0 = B_ROW0 + 2 * p;
            colbase = s * B_COLS;
            niter = B_COLS / 4;
        }

        const float4* __restrict__ r0 =
            (const float4*)(L + (size_t)row0 * NVERT + colbase);
        const float4* __restrict__ r1 = r0 + (NVERT / 4);

        const float4* __restrict__ xs0 = (const float4*)(sx + 0 * NVERT + colbase);
        const float4* __restrict__ xs1 = (const float4*)(sx + 1 * NVERT + colbase);
        const float4* __restrict__ xs2 = (const float4*)(sx + 2 * NVERT + colbase);

        float a00 = 0.f, a01 = 0.f, a02 = 0.f;
        float a10 = 0.f, a11 = 0.f, a12 = 0.f;

        #pragma unroll 4
        for (int i = lane; i < niter; i += 32) {
            float4 l0 = __ldcs(r0 + i);   // streaming: L has zero reuse
            float4 l1 = __ldcs(r1 + i);
            float4 v0 = xs0[i];
            float4 v1 = xs1[i];
            float4 v2 = xs2[i];

            a00 += l0.x * v0.x + l0.y * v0.y + l0.z * v0.z + l0.w * v0.w;
            a01 += l0.x * v1.x + l0.y * v1.y + l0.z * v1.z + l0.w * v1.w;
            a02 += l0.x * v2.x + l0.y * v2.y + l0.z * v2.z + l0.w * v2.w;
            a10 += l1.x * v0.x + l1.y * v0.y + l1.z * v0.z + l1.w * v0.w;
            a11 += l1.x * v1.x + l1.y * v1.y + l1.z * v1.z + l1.w * v1.w;
            a12 += l1.x * v2.x + l1.y * v2.y + l1.z * v2.z + l1.w * v2.w;
        }

        #pragma unroll
        for (int off = 16; off > 0; off >>= 1) {
            a00 += __shfl_xor_sync(0xFFFFFFFFu, a00, off);
            a01 += __shfl_xor_sync(0xFFFFFFFFu, a01, off);
            a02 += __shfl_xor_sync(0xFFFFFFFFu, a02, off);
            a10 += __shfl_xor_sync(0xFFFFFFFFu, a10, off);
            a11 += __shfl_xor_sync(0xFFFFFFFFu, a11, off);
            a12 += __shfl_xor_sync(0xFFFFFFFFu, a12, off);
        }

        if (lane < 6) {
            float v;
            switch (lane) {
                case 0: v = a00; break;
                case 1: v = a01; break;
                case 2: v = a02; break;
                case 3: v = a10; break;
                case 4: v = a11; break;
                default: v = a12; break;
            }
            const int row = row0 + (lane >= 3 ? 1 : 0);
            const int c   = (lane >= 3) ? (lane - 3) : lane;
            if (u < A_UNITS) {
                const int q = (int)(u & 3);
                g_y4[(q * NVERT + row) * 3 + c] = v;
            } else {
                const int s = (int)((u - A_UNITS) & (B_SLICES - 1));
                g_yB[(s * (2 * B_PAIRS) + (row - B_ROW0)) * 3 + c] = v;
            }
        }
    }

    // ---------------- Finisher election ----------------
    // Each warp signs off exactly once. The warp that observes the final
    // count knows ALL unit writes are globally visible (fence + atomic order)
    // and flags its own block as the finisher.
    if (lane == 0) {
        __threadfence();                       // publish this warp's writes
        unsigned int d = atomicAdd(&g_done, 1u);
        if (d == NWARPS - 1) {
            __threadfence();                   // acquire: all g_y writes visible
            s_fin = 1;
        }
    }
    __syncthreads();
    if (s_fin == 0) return;                    // non-finisher blocks exit

    // ---------------- Finisher block: reduce partials, write result -------
    // Fixed slice order -> bit-deterministic regardless of which block runs it.
    float s = 0.f;
    {
        // Tier A: rows 0..15359 -> 11520 float4 per q-slice (stride 12288).
        const float4* __restrict__ yv = (const float4*)g_y4;
        const int totalA = (B_ROW0 * 3) / 4;          // 11520
        const int sliceStride = (NVERT * 3) / 4;      // 12288
        for (int i = threadIdx.x; i < totalA; i += BLOCK) {
            float4 a = yv[i];
            float4 b = yv[i + sliceStride];
            float4 c = yv[i + 2 * sliceStride];
            float4 d = yv[i + 3 * sliceStride];
            float vx = a.x + b.x + c.x + d.x;
            float vy = a.y + b.y + c.y + d.y;
            float vz = a.z + b.z + c.z + d.z;
            float vw = a.w + b.w + c.w + d.w;
            s += vx * vx + vy * vy + vz * vz + vw * vw;
        }
    }
    {
        // Tier B: 1024 rows -> 768 float4 per slice, 16 slices.
        const float4* __restrict__ yv = (const float4*)g_yB;
        const int totalB = (2 * B_PAIRS * 3) / 4;     // 768
        for (int i = threadIdx.x; i < totalB; i += BLOCK) {
            float4 a = yv[i];
            #pragma unroll
            for (int j = 1; j < B_SLICES; j++) {
                float4 b = yv[i + j * totalB];
                a.x += b.x; a.y += b.y; a.z += b.z; a.w += b.w;
            }
            s += a.x * a.x + a.y * a.y + a.z * a.z + a.w * a.w;
        }
    }

    // Block reduction (fixed shape -> deterministic)
    #pragma unroll
    for (int off = 16; off > 0; off >>= 1)
        s += __shfl_xor_sync(0xFFFFFFFFu, s, off);
    const int wid = threadIdx.x >> 5;
    if (lane == 0) red[wid] = s;
    __syncthreads();
    if (wid == 0) {
        float t = (lane < (BLOCK >> 5)) ? red[lane] : 0.f;
        #pragma unroll
        for (int off = 16; off > 0; off >>= 1)
            t += __shfl_xor_sync(0xFFFFFFFFu, t, off);
        if (lane == 0) {
            out[0]   = t;
            g_ticket = 0;   // safe: all warps already signed off
            g_done   = 0;
            __threadfence();
        }
    }
}

extern "C" void kernel_launch(void* const* d_in, const int* in_sizes, int n_in,
                              void* d_out, int out_size) {
    // Identify inputs by element count: x has NVERT*3, L has NVERT*NVERT.
    const float* x = (const float*)d_in[0];
    const float* L = (const float*)d_in[1];
    if (in_sizes[0] != NVERT * 3) {
        x = (const float*)d_in[1];
        L = (const float*)d_in[0];
    }
    float* out = (float*)d_out;

    cudaFuncSetAttribute(lap_fused_kernel,
                         cudaFuncAttributeMaxDynamicSharedMemorySize,
                         (int)SMEM_BYTES);

    lap_fused_kernel<<<GRID, BLOCK, SMEM_BYTES>>>(L, x, out);
}